// round 15
// baseline (speedup 1.0000x reference)
#include <cuda_runtime.h>
#include <cuda_fp16.h>
#include <cstdint>

#define B_DIM   16384
#define N_DIM   1024
#define EMB     128
#define N_WORD  100000

#define BM 128
#define BN 128
#define NCHUNK 72
#define THREADS 256
#define NSTAGE 6

#define STAGE_BYTES 16384          // A 8KB + B 8KB, XOR-swizzled
#define IDS_W_BYTES 9216           // 128 x 18 int32
#define IDS_BYTES   13312          // + 128 x 32 int8
#define GEMM_OFF    IDS_BYTES
#define UNION_BYTES (NSTAGE * STAGE_BYTES)       // 98304 (3 fp16 table bufs fit)
#define WO_OFF      (GEMM_OFF + UNION_BYTES)     // 111616
#define SMEM_BYTES  (WO_OFF + 2048)              // 113664 (x2 CTA = 227328)

#define TSTRH 68                   // table row stride in half2 words (272B, 16B-aligned)
#define TBH_WORDS (48 * TSTRH)     // 3264 words = 13056 B per table buffer

// ---- device scratch ----
__device__ uint32_t g_Ap[(size_t)N_WORD * 64];     // word emb, half2 k-pairs
__device__ uint32_t g_Bp2[(size_t)N_DIM * 1152];   // W_h word slice, n-major half2
__device__ uint32_t g_Th[(size_t)1344 * 512];      // tag/deprel tables, half2
__device__ float    g_part[(size_t)32 * B_DIM * 3];

// ---- helpers ----
__device__ __forceinline__ uint32_t smem_u32(const void* p) {
    uint32_t a;
    asm("{ .reg .u64 t; cvta.to.shared.u64 t, %1; cvt.u32.u64 %0, t; }" : "=r"(a) : "l"(p));
    return a;
}
__device__ __forceinline__ void cp16(uint32_t dst, const void* src) {
    asm volatile("cp.async.cg.shared.global [%0], [%1], 16;" :: "r"(dst), "l"(src) : "memory");
}
#define CP_COMMIT() asm volatile("cp.async.commit_group;" ::: "memory")
#define CP_WAIT(n)  asm volatile("cp.async.wait_group %0;" :: "n"(n) : "memory")

__device__ __forceinline__ uint32_t pack2(float a, float b) {
    __half2 h = __floats2half2_rn(a, b);
    return *(uint32_t*)&h;
}
__device__ __forceinline__ void ldsm4(uint32_t r[4], uint32_t addr) {
    asm volatile("ldmatrix.sync.aligned.m8n8.x4.shared.b16 {%0,%1,%2,%3}, [%4];"
                 : "=r"(r[0]), "=r"(r[1]), "=r"(r[2]), "=r"(r[3]) : "r"(addr));
}
__device__ __forceinline__ void mma_f16(float c[4], uint32_t a0, uint32_t a1,
                                        uint32_t a2, uint32_t a3,
                                        uint32_t b0, uint32_t b1) {
    asm volatile(
        "mma.sync.aligned.m16n8k16.row.col.f32.f16.f16.f32 "
        "{%0,%1,%2,%3},{%4,%5,%6,%7},{%8,%9},{%0,%1,%2,%3};"
        : "+f"(c[0]), "+f"(c[1]), "+f"(c[2]), "+f"(c[3])
        : "r"(a0), "r"(a1), "r"(a2), "r"(a3), "r"(b0), "r"(b1));
}
// swizzled word offset inside an 8KB (128 rows x 16 words) region
__device__ __forceinline__ uint32_t woff(int row, int grp) {
    return (uint32_t)(row * 16 + 4 * (grp ^ ((row >> 1) & 3)));
}

// ---------------------------------------------------------------------------
// Prep kernels
// ---------------------------------------------------------------------------
__global__ void pack_e16(const float* __restrict__ wemb)
{
    const size_t i = (size_t)blockIdx.x * 256 + threadIdx.x;
    if (i >= (size_t)N_WORD * 32) return;
    const float4 v = ((const float4*)wemb)[i];
    *(uint2*)&g_Ap[2 * i] = make_uint2(pack2(v.x, v.y), pack2(v.z, v.w));
}

__global__ void pack_whp(const float* __restrict__ Wh)
{
    __shared__ float sm[128][65];
    const int t  = threadIdx.x;
    const int kb = blockIdx.x;
    const int nb = blockIdx.y;
#pragma unroll
    for (int i = 0; i < 32; ++i) {
        const int idx = t + 256 * i;
        const int r = idx >> 6, c = idx & 63;
        sm[r][c] = Wh[(size_t)(kb * 128 + r) * N_DIM + nb * 64 + c];
    }
    __syncthreads();
#pragma unroll
    for (int i = 0; i < 16; ++i) {
        const int idx = t + 256 * i;
        const int n = idx >> 6, kp = idx & 63;
        g_Bp2[(size_t)(nb * 64 + n) * 1152 + kb * 64 + kp] =
            pack2(sm[2 * kp][n], sm[2 * kp + 1][n]);
    }
}

// T[(f,v)][n-pair] = half2 of exact fp32 dot
__global__ void build_tables(const float* __restrict__ temb,
                             const float* __restrict__ demb,
                             const float* __restrict__ Wh)
{
    extern __shared__ float bs[];
    float* Ws = bs;            // [128][128]
    float* es = bs + 16384;    // [16][128]

    const int f = blockIdx.x, ct = blockIdx.y, z = blockIdx.z;
    const int t = threadIdx.x;
    const bool tag = (f < 18);
    const int nv    = tag ? 48 : 40;
    const int wrow0 = (tag ? (18 + f) : (36 + (f - 18))) * EMB;
    const int tbase = tag ? f * 48 : 864 + (f - 18) * 40;
    const float* E  = tag ? temb : demb;

    for (int i = t; i < 16384; i += 256) {
        const int k = i >> 7, c = i & 127;
        Ws[i] = Wh[(size_t)(wrow0 + k) * N_DIM + ct * 128 + c];
    }
    for (int i = t; i < 2048; i += 256) {
        const int v = z * 16 + (i >> 7), c = i & 127;
        es[i] = (v < nv) ? E[v * EMB + c] : 0.0f;
    }
    __syncthreads();

    const int c2 = (t & 63) * 2;
    const int vl = t >> 6;
    float s[4][2];
#pragma unroll
    for (int j = 0; j < 4; ++j) { s[j][0] = 0.0f; s[j][1] = 0.0f; }
    for (int k = 0; k < 128; ++k) {
        const float w0 = Ws[k * 128 + c2];
        const float w1 = Ws[k * 128 + c2 + 1];
#pragma unroll
        for (int j = 0; j < 4; ++j) {
            const float e = es[(vl + 4 * j) * 128 + k];
            s[j][0] = fmaf(e, w0, s[j][0]);
            s[j][1] = fmaf(e, w1, s[j][1]);
        }
    }
#pragma unroll
    for (int j = 0; j < 4; ++j) {
        const int v = z * 16 + vl + 4 * j;
        if (v < nv)
            g_Th[(size_t)(tbase + v) * 512 + ct * 64 + (c2 >> 1)] = pack2(s[j][0], s[j][1]);
    }
}

// ---------------------------------------------------------------------------
// GEMM1: 8 warps (2m x 4n), warp tile 64x32, 6-stage pipeline, 2 CTAs/SM
// ---------------------------------------------------------------------------
__global__ __launch_bounds__(THREADS, 2)
void gemm1_mma(const int* __restrict__ wid, const int* __restrict__ tgid,
               const int* __restrict__ did,
               const float* __restrict__ bh, const float* __restrict__ Wo)
{
    extern __shared__ char sm[];
    int*   ids_w  = (int*)sm;                          // [128][18]
    char*  ids_td = (char*)(sm + IDS_W_BYTES);         // [128][32]
    float* wo     = (float*)(sm + WO_OFF);

    const int t    = threadIdx.x;
    const int lane = t & 31;
    const int w    = t >> 5;
    const int g    = lane >> 2;
    const int tig  = lane & 3;
    const int wm   = w & 1;
    const int wn   = w >> 1;
    const int m0w  = wm * 64;
    const int n0w  = wn * 32;
    const int m_blk = blockIdx.y * BM;
    const int n0    = blockIdx.x * BN;

    const uint32_t sbase  = smem_u32(sm);
    const uint32_t g_u32  = sbase + GEMM_OFF;
    const uint32_t t_u32  = sbase + GEMM_OFF;

    for (int i = t; i < 128 * 18; i += THREADS) {
        const int row = i / 18, f = i - row * 18;
        ids_w[row * 18 + f] = wid[(m_blk + row) * 18 + f];
    }
    for (int i = t; i < 128 * 30; i += THREADS) {
        const int row = i / 30, f = i - row * 30;
        const int v = (f < 18) ? tgid[(m_blk + row) * 18 + f]
                               : did [(m_blk + row) * 12 + (f - 18)];
        ids_td[row * 32 + f] = (char)v;
    }
    for (int i = t; i < 384; i += THREADS)
        wo[i] = Wo[(size_t)n0 * 3 + i];
    __syncthreads();

    float acc[4][4][4];
#pragma unroll
    for (int i = 0; i < 4; ++i)
#pragma unroll
        for (int j = 0; j < 4; ++j)
#pragma unroll
            for (int q = 0; q < 4; ++q) acc[i][j][q] = 0.0f;

    // ldmatrix per-lane addresses (byte offsets inside a stage)
    const uint32_t a_base = (uint32_t)((m0w + (lane & 15)) * 64);
    const uint32_t asw    = ((lane & 15) >> 1) & 3;
    uint32_t ag[2];
    ag[0] = (uint32_t)(((0 + (lane >> 4)) ^ asw) * 16);
    ag[1] = (uint32_t)(((2 + (lane >> 4)) ^ asw) * 16);
    const int brow = n0w + (lane & 7) + 8 * (lane >> 4);
    const uint32_t b_base = 8192u + (uint32_t)(brow * 64);
    const uint32_t bsw    = (uint32_t)((brow >> 1) & 3);
    uint32_t bg[2];
    bg[0] = (uint32_t)(((0 + ((lane >> 3) & 1)) ^ bsw) * 16);
    bg[1] = (uint32_t)(((2 + ((lane >> 3) & 1)) ^ bsw) * 16);

    auto issueG = [&](int c, int slot) {
        const int f   = c >> 2;
        const int kpo = (c & 3) * 16;
        const uint32_t ab = g_u32 + slot * STAGE_BYTES;
        const uint32_t bb = ab + 8192;
#pragma unroll
        for (int r = 0; r < 2; ++r) {
            const int idx = t + 256 * r;
            const int row = idx >> 2, grp = idx & 3;
            const int id  = ids_w[row * 18 + f];
            cp16(ab + woff(row, grp) * 4, g_Ap + (size_t)id * 64 + kpo + 4 * grp);
        }
#pragma unroll
        for (int r = 0; r < 2; ++r) {
            const int idx = t + 256 * r;
            const int row = idx >> 2, grp = idx & 3;
            cp16(bb + woff(row, grp) * 4,
                 g_Bp2 + (size_t)(n0 + row) * 1152 + c * 16 + 4 * grp);
        }
    };

    issueG(0, 0); CP_COMMIT();
    issueG(1, 1); CP_COMMIT();
    issueG(2, 2); CP_COMMIT();
    issueG(3, 3); CP_COMMIT();
    issueG(4, 4); CP_COMMIT();

    int slot_c = 0, slot_i = 5;
    for (int c = 0; c < NCHUNK; ++c) {
        CP_WAIT(4);
        __syncthreads();
        if (c + 5 < NCHUNK) {
            issueG(c + 5, slot_i);
            if (++slot_i == NSTAGE) slot_i = 0;
        }
        CP_COMMIT();

        const uint32_t st = g_u32 + slot_c * STAGE_BYTES;
        if (++slot_c == NSTAGE) slot_c = 0;

        uint32_t a[2][4][4], b[2][2][4];
#pragma unroll
        for (int s = 0; s < 2; ++s) {
#pragma unroll
            for (int mt = 0; mt < 4; ++mt)
                ldsm4(a[s][mt], st + a_base + mt * 1024 + ag[s]);
#pragma unroll
            for (int p = 0; p < 2; ++p)
                ldsm4(b[s][p], st + b_base + p * 1024 + bg[s]);
        }
#pragma unroll
        for (int s = 0; s < 2; ++s)
#pragma unroll
            for (int mt = 0; mt < 4; ++mt) {
                mma_f16(acc[mt][0], a[s][mt][0], a[s][mt][1], a[s][mt][2], a[s][mt][3],
                        b[s][0][0], b[s][0][1]);
                mma_f16(acc[mt][1], a[s][mt][0], a[s][mt][1], a[s][mt][2], a[s][mt][3],
                        b[s][0][2], b[s][0][3]);
                mma_f16(acc[mt][2], a[s][mt][0], a[s][mt][1], a[s][mt][2], a[s][mt][3],
                        b[s][1][0], b[s][1][1]);
                mma_f16(acc[mt][3], a[s][mt][0], a[s][mt][1], a[s][mt][2], a[s][mt][3],
                        b[s][1][2], b[s][1][3]);
            }
    }
    __syncthreads();   // mainloop smem reads done before table bufs overwrite

    // ---- table accumulation: 30 features, fp16 tables, 3 cp.async buffers ----
    auto issueT = [&](int f, int st) {
        const bool tag = (f < 18);
        const int nv    = tag ? 48 : 40;
        const int tbase = tag ? f * 48 : 864 + (f - 18) * 40;
        const int tot   = nv * 16;          // cp16 per slice
        const uint32_t db = t_u32 + st * TBH_WORDS * 4;
        for (int i = t; i < tot; i += THREADS) {
            const int v = i >> 4, q = i & 15;
            cp16(db + (v * TSTRH + 4 * q) * 4,
                 g_Th + (size_t)(tbase + v) * 512 + (n0 >> 1) + 4 * q);
        }
    };

    issueT(0, 0); CP_COMMIT();
    issueT(1, 1); CP_COMMIT();
    issueT(2, 2); CP_COMMIT();
    for (int f = 0; f < 30; ++f) {
        CP_WAIT(2);
        __syncthreads();

        const int tb = f % 3;
        const uint32_t* T = (const uint32_t*)(sm + GEMM_OFF) + tb * TBH_WORDS;
#pragma unroll
        for (int mt = 0; mt < 4; ++mt) {
            const int r0  = m0w + 16 * mt + g;
            const int id0 = ids_td[r0 * 32 + f];
            const int id1 = ids_td[(r0 + 8) * 32 + f];
            const uint32_t* t0 = T + id0 * TSTRH + (n0w >> 1);
            const uint32_t* t1 = T + id1 * TSTRH + (n0w >> 1);
#pragma unroll
            for (int nt = 0; nt < 4; ++nt) {
                const uint32_t u0 = t0[4 * nt + tig];
                const uint32_t u1 = t1[4 * nt + tig];
                const float2 v0 = __half22float2(*(const __half2*)&u0);
                const float2 v1 = __half22float2(*(const __half2*)&u1);
                acc[mt][nt][0] += v0.x;  acc[mt][nt][1] += v0.y;
                acc[mt][nt][2] += v1.x;  acc[mt][nt][3] += v1.y;
            }
        }
        __syncthreads();
        if (f + 3 < 30) issueT(f + 3, tb);
        CP_COMMIT();
    }

    // ---- epilogue: bias + relu + partial dot with W_o slice ----
    float p2[4][2][3];
#pragma unroll
    for (int mt = 0; mt < 4; ++mt)
#pragma unroll
        for (int h = 0; h < 2; ++h)
#pragma unroll
            for (int cc = 0; cc < 3; ++cc) p2[mt][h][cc] = 0.0f;

#pragma unroll
    for (int nt = 0; nt < 4; ++nt) {
        const int colq = n0w + 8 * nt + 2 * tig;
        const float w00 = wo[colq * 3 + 0], w01 = wo[colq * 3 + 1], w02 = wo[colq * 3 + 2];
        const float w10 = wo[colq * 3 + 3], w11 = wo[colq * 3 + 4], w12 = wo[colq * 3 + 5];
        const float2 bb = *(const float2*)&bh[n0 + colq];
#pragma unroll
        for (int mt = 0; mt < 4; ++mt) {
            float v0 = acc[mt][nt][0] + bb.x;
            float v1 = acc[mt][nt][1] + bb.y;
            float v2 = acc[mt][nt][2] + bb.x;
            float v3 = acc[mt][nt][3] + bb.y;
            v0 = v0 > 0.f ? v0 : 0.f;  v1 = v1 > 0.f ? v1 : 0.f;
            v2 = v2 > 0.f ? v2 : 0.f;  v3 = v3 > 0.f ? v3 : 0.f;
            p2[mt][0][0] += v0 * w00 + v1 * w10;
            p2[mt][0][1] += v0 * w01 + v1 * w11;
            p2[mt][0][2] += v0 * w02 + v1 * w12;
            p2[mt][1][0] += v2 * w00 + v3 * w10;
            p2[mt][1][1] += v2 * w01 + v3 * w11;
            p2[mt][1][2] += v2 * w02 + v3 * w12;
        }
    }
#pragma unroll
    for (int mt = 0; mt < 4; ++mt)
#pragma unroll
        for (int h = 0; h < 2; ++h)
#pragma unroll
            for (int cc = 0; cc < 3; ++cc) {
                float x = p2[mt][h][cc];
                x += __shfl_xor_sync(0xffffffffu, x, 1);
                x += __shfl_xor_sync(0xffffffffu, x, 2);
                p2[mt][h][cc] = x;
            }
    if (tig == 0) {
        const int slot = blockIdx.x * 4 + wn;
#pragma unroll
        for (int mt = 0; mt < 4; ++mt)
#pragma unroll
            for (int h = 0; h < 2; ++h) {
                const int row = m_blk + m0w + 16 * mt + g + 8 * h;
                float* dst = g_part + ((size_t)slot * B_DIM + row) * 3;
                dst[0] = p2[mt][h][0];
                dst[1] = p2[mt][h][1];
                dst[2] = p2[mt][h][2];
            }
    }
}

// ---------------------------------------------------------------------------
__global__ __launch_bounds__(256)
void reduce_out(const float* __restrict__ bo, float* __restrict__ out)
{
    const int row = blockIdx.x * 256 + threadIdx.x;
    float s0 = bo[0], s1 = bo[1], s2 = bo[2];
#pragma unroll
    for (int sl = 0; sl < 32; ++sl) {
        const float* p = g_part + ((size_t)sl * B_DIM + row) * 3;
        s0 += p[0]; s1 += p[1]; s2 += p[2];
    }
    out[row * 3 + 0] = s0;
    out[row * 3 + 1] = s1;
    out[row * 3 + 2] = s2;
}

extern "C" void kernel_launch(void* const* d_in, const int* in_sizes, int n_in,
                              void* d_out, int out_size)
{
    const int*   wid  = (const int*)d_in[0];
    const int*   tgid = (const int*)d_in[1];
    const int*   did  = (const int*)d_in[2];
    const float* wemb = (const float*)d_in[3];
    const float* temb = (const float*)d_in[4];
    const float* demb = (const float*)d_in[5];
    const float* Wh   = (const float*)d_in[6];
    const float* bh   = (const float*)d_in[7];
    const float* Wo   = (const float*)d_in[8];
    const float* bo   = (const float*)d_in[9];
    float* out = (float*)d_out;

    cudaFuncSetAttribute(build_tables,
                         cudaFuncAttributeMaxDynamicSharedMemorySize, 73728);
    cudaFuncSetAttribute(gemm1_mma,
                         cudaFuncAttributeMaxDynamicSharedMemorySize, SMEM_BYTES);

    pack_e16<<<(N_WORD * 32 + 255) / 256, 256>>>(wemb);
    pack_whp<<<dim3(18, 16), 256>>>(Wh);
    build_tables<<<dim3(30, 8, 3), 256, 73728>>>(temb, demb, Wh);

    gemm1_mma<<<dim3(N_DIM / BN, B_DIM / BM), THREADS, SMEM_BYTES>>>(
        wid, tgid, did, bh, Wo);

    reduce_out<<<B_DIM / 256, 256>>>(bo, out);
}

// round 16
// speedup vs baseline: 1.5185x; 1.5185x over previous
#include <cuda_runtime.h>
#include <cuda_fp16.h>
#include <cstdint>

#define B_DIM   16384
#define N_DIM   1024
#define EMB     128
#define N_WORD  100000

#define BM 128
#define BN 128
#define NCHUNK 72
#define THREADS 256
#define NSTAGE 5

#define STAGE_BYTES 16384          // A 8KB + B 8KB, XOR-swizzled
#define IDS_W_BYTES 9216           // 128 x 18 int32
#define IDS_BYTES   13312          // + 128 x 32 int8
#define GEMM_OFF    IDS_BYTES
#define UNION_BYTES (NSTAGE * STAGE_BYTES)       // 81920 (3 fp16 table bufs = 39168 fit)
#define WO_OFF      (GEMM_OFF + UNION_BYTES)     // 95232
#define SMEM_BYTES  (WO_OFF + 2048)              // 97280  (x2 CTA = 194560)

#define TSTRH 68                   // table row stride in half2 words (272B, 16B-aligned)
#define TBH_WORDS (48 * TSTRH)     // 3264 words = 13056 B per table buffer

// ---- device scratch ----
__device__ uint32_t g_Ap[(size_t)N_WORD * 64];     // word emb, half2 k-pairs
__device__ uint32_t g_Bp2[(size_t)N_DIM * 1152];   // W_h word slice, n-major half2
__device__ uint32_t g_Th[(size_t)1344 * 512];      // tag/deprel tables, half2
__device__ float    g_part[(size_t)32 * B_DIM * 3];

// ---- helpers ----
__device__ __forceinline__ uint32_t smem_u32(const void* p) {
    uint32_t a;
    asm("{ .reg .u64 t; cvta.to.shared.u64 t, %1; cvt.u32.u64 %0, t; }" : "=r"(a) : "l"(p));
    return a;
}
__device__ __forceinline__ void cp16(uint32_t dst, const void* src) {
    asm volatile("cp.async.cg.shared.global [%0], [%1], 16;" :: "r"(dst), "l"(src) : "memory");
}
#define CP_COMMIT() asm volatile("cp.async.commit_group;" ::: "memory")
#define CP_WAIT(n)  asm volatile("cp.async.wait_group %0;" :: "n"(n) : "memory")

__device__ __forceinline__ uint32_t pack2(float a, float b) {
    __half2 h = __floats2half2_rn(a, b);
    return *(uint32_t*)&h;
}
__device__ __forceinline__ void ldsm4(uint32_t r[4], uint32_t addr) {
    asm volatile("ldmatrix.sync.aligned.m8n8.x4.shared.b16 {%0,%1,%2,%3}, [%4];"
                 : "=r"(r[0]), "=r"(r[1]), "=r"(r[2]), "=r"(r[3]) : "r"(addr));
}
__device__ __forceinline__ void mma_f16(float c[4], uint32_t a0, uint32_t a1,
                                        uint32_t a2, uint32_t a3,
                                        uint32_t b0, uint32_t b1) {
    asm volatile(
        "mma.sync.aligned.m16n8k16.row.col.f32.f16.f16.f32 "
        "{%0,%1,%2,%3},{%4,%5,%6,%7},{%8,%9},{%0,%1,%2,%3};"
        : "+f"(c[0]), "+f"(c[1]), "+f"(c[2]), "+f"(c[3])
        : "r"(a0), "r"(a1), "r"(a2), "r"(a3), "r"(b0), "r"(b1));
}
// swizzled word offset inside an 8KB (128 rows x 16 words) region
__device__ __forceinline__ uint32_t woff(int row, int grp) {
    return (uint32_t)(row * 16 + 4 * (grp ^ ((row >> 1) & 3)));
}

// ---------------------------------------------------------------------------
// Fused prep: blocks [0,12500) pack word embeddings; rest pack W_h word slice
// ---------------------------------------------------------------------------
#define E16_BLOCKS 12500           // N_WORD*32/256
__global__ void pack_all(const float* __restrict__ wemb, const float* __restrict__ Wh)
{
    __shared__ float sm[128][65];
    const int t = threadIdx.x;
    int b = blockIdx.x;

    if (b < E16_BLOCKS) {
        const size_t i = (size_t)b * 256 + t;
        if (i < (size_t)N_WORD * 32) {
            const float4 v = ((const float4*)wemb)[i];
            *(uint2*)&g_Ap[2 * i] = make_uint2(pack2(v.x, v.y), pack2(v.z, v.w));
        }
        return;
    }
    b -= E16_BLOCKS;
    const int kb = b >> 4;     // 18 tiles of 128 k rows
    const int nb = b & 15;     // 16 tiles of 64 n
#pragma unroll
    for (int i = 0; i < 32; ++i) {
        const int idx = t + 256 * i;
        const int r = idx >> 6, c = idx & 63;
        sm[r][c] = Wh[(size_t)(kb * 128 + r) * N_DIM + nb * 64 + c];
    }
    __syncthreads();
#pragma unroll
    for (int i = 0; i < 16; ++i) {
        const int idx = t + 256 * i;
        const int n = idx >> 6, kp = idx & 63;
        g_Bp2[(size_t)(nb * 64 + n) * 1152 + kb * 64 + kp] =
            pack2(sm[2 * kp][n], sm[2 * kp + 1][n]);
    }
}

// T[(f,v)][n-pair] = half2 of exact fp32 dot
__global__ void build_tables(const float* __restrict__ temb,
                             const float* __restrict__ demb,
                             const float* __restrict__ Wh)
{
    extern __shared__ float bs[];
    float* Ws = bs;            // [128][128]
    float* es = bs + 16384;    // [16][128]

    const int f = blockIdx.x, ct = blockIdx.y, z = blockIdx.z;
    const int t = threadIdx.x;
    const bool tag = (f < 18);
    const int nv    = tag ? 48 : 40;
    const int wrow0 = (tag ? (18 + f) : (36 + (f - 18))) * EMB;
    const int tbase = tag ? f * 48 : 864 + (f - 18) * 40;
    const float* E  = tag ? temb : demb;

    for (int i = t; i < 16384; i += 256) {
        const int k = i >> 7, c = i & 127;
        Ws[i] = Wh[(size_t)(wrow0 + k) * N_DIM + ct * 128 + c];
    }
    for (int i = t; i < 2048; i += 256) {
        const int v = z * 16 + (i >> 7), c = i & 127;
        es[i] = (v < nv) ? E[v * EMB + c] : 0.0f;
    }
    __syncthreads();

    const int c2 = (t & 63) * 2;
    const int vl = t >> 6;
    float s[4][2];
#pragma unroll
    for (int j = 0; j < 4; ++j) { s[j][0] = 0.0f; s[j][1] = 0.0f; }
    for (int k = 0; k < 128; ++k) {
        const float w0 = Ws[k * 128 + c2];
        const float w1 = Ws[k * 128 + c2 + 1];
#pragma unroll
        for (int j = 0; j < 4; ++j) {
            const float e = es[(vl + 4 * j) * 128 + k];
            s[j][0] = fmaf(e, w0, s[j][0]);
            s[j][1] = fmaf(e, w1, s[j][1]);
        }
    }
#pragma unroll
    for (int j = 0; j < 4; ++j) {
        const int v = z * 16 + vl + 4 * j;
        if (v < nv)
            g_Th[(size_t)(tbase + v) * 512 + ct * 64 + (c2 >> 1)] = pack2(s[j][0], s[j][1]);
    }
}

// ---------------------------------------------------------------------------
// GEMM1: 8 warps (2m x 4n), warp tile 64x32, 5-stage pipeline, 2 CTAs/SM
// ---------------------------------------------------------------------------
__global__ __launch_bounds__(THREADS, 2)
void gemm1_mma(const int* __restrict__ wid, const int* __restrict__ tgid,
               const int* __restrict__ did,
               const float* __restrict__ bh, const float* __restrict__ Wo)
{
    extern __shared__ char sm[];
    int*   ids_w  = (int*)sm;                          // [128][18]
    char*  ids_td = (char*)(sm + IDS_W_BYTES);         // [128][32]
    float* wo     = (float*)(sm + WO_OFF);

    const int t    = threadIdx.x;
    const int lane = t & 31;
    const int w    = t >> 5;
    const int g    = lane >> 2;
    const int tig  = lane & 3;
    const int wm   = w & 1;
    const int wn   = w >> 1;
    const int m0w  = wm * 64;
    const int n0w  = wn * 32;
    const int m_blk = blockIdx.y * BM;
    const int n0    = blockIdx.x * BN;

    const uint32_t sbase  = smem_u32(sm);
    const uint32_t g_u32  = sbase + GEMM_OFF;
    const uint32_t t_u32  = sbase + GEMM_OFF;

    for (int i = t; i < 128 * 18; i += THREADS) {
        const int row = i / 18, f = i - row * 18;
        ids_w[row * 18 + f] = wid[(m_blk + row) * 18 + f];
    }
    for (int i = t; i < 128 * 30; i += THREADS) {
        const int row = i / 30, f = i - row * 30;
        const int v = (f < 18) ? tgid[(m_blk + row) * 18 + f]
                               : did [(m_blk + row) * 12 + (f - 18)];
        ids_td[row * 32 + f] = (char)v;
    }
    for (int i = t; i < 384; i += THREADS)
        wo[i] = Wo[(size_t)n0 * 3 + i];
    __syncthreads();

    float acc[4][4][4];
#pragma unroll
    for (int i = 0; i < 4; ++i)
#pragma unroll
        for (int j = 0; j < 4; ++j)
#pragma unroll
            for (int q = 0; q < 4; ++q) acc[i][j][q] = 0.0f;

    // ldmatrix per-lane addresses (byte offsets inside a stage)
    const uint32_t a_base = (uint32_t)((m0w + (lane & 15)) * 64);
    const uint32_t asw    = ((lane & 15) >> 1) & 3;
    uint32_t ag[2];
    ag[0] = (uint32_t)(((0 + (lane >> 4)) ^ asw) * 16);
    ag[1] = (uint32_t)(((2 + (lane >> 4)) ^ asw) * 16);
    const int brow = n0w + (lane & 7) + 8 * (lane >> 4);
    const uint32_t b_base = 8192u + (uint32_t)(brow * 64);
    const uint32_t bsw    = (uint32_t)((brow >> 1) & 3);
    uint32_t bg[2];
    bg[0] = (uint32_t)(((0 + ((lane >> 3) & 1)) ^ bsw) * 16);
    bg[1] = (uint32_t)(((2 + ((lane >> 3) & 1)) ^ bsw) * 16);

    auto issueG = [&](int c, int slot) {
        const int f   = c >> 2;
        const int kpo = (c & 3) * 16;
        const uint32_t ab = g_u32 + slot * STAGE_BYTES;
        const uint32_t bb = ab + 8192;
#pragma unroll
        for (int r = 0; r < 2; ++r) {
            const int idx = t + 256 * r;
            const int row = idx >> 2, grp = idx & 3;
            const int id  = ids_w[row * 18 + f];
            cp16(ab + woff(row, grp) * 4, g_Ap + (size_t)id * 64 + kpo + 4 * grp);
        }
#pragma unroll
        for (int r = 0; r < 2; ++r) {
            const int idx = t + 256 * r;
            const int row = idx >> 2, grp = idx & 3;
            cp16(bb + woff(row, grp) * 4,
                 g_Bp2 + (size_t)(n0 + row) * 1152 + c * 16 + 4 * grp);
        }
    };

    issueG(0, 0); CP_COMMIT();
    issueG(1, 1); CP_COMMIT();
    issueG(2, 2); CP_COMMIT();
    issueG(3, 3); CP_COMMIT();

    int slot_c = 0, slot_i = 4;
    for (int c = 0; c < NCHUNK; ++c) {
        CP_WAIT(3);
        __syncthreads();
        if (c + 4 < NCHUNK) {
            issueG(c + 4, slot_i);
            if (++slot_i == NSTAGE) slot_i = 0;
        }
        CP_COMMIT();

        const uint32_t st = g_u32 + slot_c * STAGE_BYTES;
        if (++slot_c == NSTAGE) slot_c = 0;

        uint32_t a[2][4][4], b[2][2][4];
#pragma unroll
        for (int s = 0; s < 2; ++s) {
#pragma unroll
            for (int mt = 0; mt < 4; ++mt)
                ldsm4(a[s][mt], st + a_base + mt * 1024 + ag[s]);
#pragma unroll
            for (int p = 0; p < 2; ++p)
                ldsm4(b[s][p], st + b_base + p * 1024 + bg[s]);
        }
#pragma unroll
        for (int s = 0; s < 2; ++s)
#pragma unroll
            for (int mt = 0; mt < 4; ++mt) {
                mma_f16(acc[mt][0], a[s][mt][0], a[s][mt][1], a[s][mt][2], a[s][mt][3],
                        b[s][0][0], b[s][0][1]);
                mma_f16(acc[mt][1], a[s][mt][0], a[s][mt][1], a[s][mt][2], a[s][mt][3],
                        b[s][0][2], b[s][0][3]);
                mma_f16(acc[mt][2], a[s][mt][0], a[s][mt][1], a[s][mt][2], a[s][mt][3],
                        b[s][1][0], b[s][1][1]);
                mma_f16(acc[mt][3], a[s][mt][0], a[s][mt][1], a[s][mt][2], a[s][mt][3],
                        b[s][1][2], b[s][1][3]);
            }
    }
    __syncthreads();   // mainloop smem reads done before table bufs overwrite

    // ---- table phase: 30 features, fp16 tables, 3 buffers, issue-2-ahead,
    //      single sync per feature ----
    auto issueT = [&](int f, int st) {
        const bool tag = (f < 18);
        const int nv    = tag ? 48 : 40;
        const int tbase = tag ? f * 48 : 864 + (f - 18) * 40;
        const int tot   = nv * 16;          // cp16 per slice
        const uint32_t db = t_u32 + st * TBH_WORDS * 4;
        for (int i = t; i < tot; i += THREADS) {
            const int v = i >> 4, q = i & 15;
            cp16(db + (v * TSTRH + 4 * q) * 4,
                 g_Th + (size_t)(tbase + v) * 512 + (n0 >> 1) + 4 * q);
        }
    };

    issueT(0, 0); CP_COMMIT();
    issueT(1, 1); CP_COMMIT();
    for (int f = 0; f < 30; ++f) {
        CP_WAIT(1);
        __syncthreads();
        // refill buffer (f+2)%3 — last read at iteration f-1, fenced by the sync above
        if (f + 2 < 30) issueT(f + 2, (f + 2) % 3);
        CP_COMMIT();

        const uint32_t* T = (const uint32_t*)(sm + GEMM_OFF) + (f % 3) * TBH_WORDS;
#pragma unroll
        for (int mt = 0; mt < 4; ++mt) {
            const int r0  = m0w + 16 * mt + g;
            const int id0 = ids_td[r0 * 32 + f];
            const int id1 = ids_td[(r0 + 8) * 32 + f];
            const uint32_t* t0 = T + id0 * TSTRH + (n0w >> 1);
            const uint32_t* t1 = T + id1 * TSTRH + (n0w >> 1);
#pragma unroll
            for (int nt = 0; nt < 4; ++nt) {
                const uint32_t u0 = t0[4 * nt + tig];
                const uint32_t u1 = t1[4 * nt + tig];
                const float2 v0 = __half22float2(*(const __half2*)&u0);
                const float2 v1 = __half22float2(*(const __half2*)&u1);
                acc[mt][nt][0] += v0.x;  acc[mt][nt][1] += v0.y;
                acc[mt][nt][2] += v1.x;  acc[mt][nt][3] += v1.y;
            }
        }
    }

    // ---- epilogue: bias + relu + partial dot with W_o slice ----
    float p2[4][2][3];
#pragma unroll
    for (int mt = 0; mt < 4; ++mt)
#pragma unroll
        for (int h = 0; h < 2; ++h)
#pragma unroll
            for (int cc = 0; cc < 3; ++cc) p2[mt][h][cc] = 0.0f;

#pragma unroll
    for (int nt = 0; nt < 4; ++nt) {
        const int colq = n0w + 8 * nt + 2 * tig;
        const float w00 = wo[colq * 3 + 0], w01 = wo[colq * 3 + 1], w02 = wo[colq * 3 + 2];
        const float w10 = wo[colq * 3 + 3], w11 = wo[colq * 3 + 4], w12 = wo[colq * 3 + 5];
        const float2 bb = *(const float2*)&bh[n0 + colq];
#pragma unroll
        for (int mt = 0; mt < 4; ++mt) {
            float v0 = acc[mt][nt][0] + bb.x;
            float v1 = acc[mt][nt][1] + bb.y;
            float v2 = acc[mt][nt][2] + bb.x;
            float v3 = acc[mt][nt][3] + bb.y;
            v0 = v0 > 0.f ? v0 : 0.f;  v1 = v1 > 0.f ? v1 : 0.f;
            v2 = v2 > 0.f ? v2 : 0.f;  v3 = v3 > 0.f ? v3 : 0.f;
            p2[mt][0][0] += v0 * w00 + v1 * w10;
            p2[mt][0][1] += v0 * w01 + v1 * w11;
            p2[mt][0][2] += v0 * w02 + v1 * w12;
            p2[mt][1][0] += v2 * w00 + v3 * w10;
            p2[mt][1][1] += v2 * w01 + v3 * w11;
            p2[mt][1][2] += v2 * w02 + v3 * w12;
        }
    }
#pragma unroll
    for (int mt = 0; mt < 4; ++mt)
#pragma unroll
        for (int h = 0; h < 2; ++h)
#pragma unroll
            for (int cc = 0; cc < 3; ++cc) {
                float x = p2[mt][h][cc];
                x += __shfl_xor_sync(0xffffffffu, x, 1);
                x += __shfl_xor_sync(0xffffffffu, x, 2);
                p2[mt][h][cc] = x;
            }
    if (tig == 0) {
        const int slot = blockIdx.x * 4 + wn;
#pragma unroll
        for (int mt = 0; mt < 4; ++mt)
#pragma unroll
            for (int h = 0; h < 2; ++h) {
                const int row = m_blk + m0w + 16 * mt + g + 8 * h;
                float* dst = g_part + ((size_t)slot * B_DIM + row) * 3;
                dst[0] = p2[mt][h][0];
                dst[1] = p2[mt][h][1];
                dst[2] = p2[mt][h][2];
            }
    }
}

// ---------------------------------------------------------------------------
__global__ __launch_bounds__(256)
void reduce_out(const float* __restrict__ bo, float* __restrict__ out)
{
    const int row = blockIdx.x * 256 + threadIdx.x;
    float s0 = bo[0], s1 = bo[1], s2 = bo[2];
#pragma unroll
    for (int sl = 0; sl < 32; ++sl) {
        const float* p = g_part + ((size_t)sl * B_DIM + row) * 3;
        s0 += p[0]; s1 += p[1]; s2 += p[2];
    }
    out[row * 3 + 0] = s0;
    out[row * 3 + 1] = s1;
    out[row * 3 + 2] = s2;
}

extern "C" void kernel_launch(void* const* d_in, const int* in_sizes, int n_in,
                              void* d_out, int out_size)
{
    const int*   wid  = (const int*)d_in[0];
    const int*   tgid = (const int*)d_in[1];
    const int*   did  = (const int*)d_in[2];
    const float* wemb = (const float*)d_in[3];
    const float* temb = (const float*)d_in[4];
    const float* demb = (const float*)d_in[5];
    const float* Wh   = (const float*)d_in[6];
    const float* bh   = (const float*)d_in[7];
    const float* Wo   = (const float*)d_in[8];
    const float* bo   = (const float*)d_in[9];
    float* out = (float*)d_out;

    cudaFuncSetAttribute(build_tables,
                         cudaFuncAttributeMaxDynamicSharedMemorySize, 73728);
    cudaFuncSetAttribute(gemm1_mma,
                         cudaFuncAttributeMaxDynamicSharedMemorySize, SMEM_BYTES);

    pack_all<<<E16_BLOCKS + 288, 256>>>(wemb, Wh);
    build_tables<<<dim3(30, 8, 3), 256, 73728>>>(temb, demb, Wh);

    gemm1_mma<<<dim3(N_DIM / BN, B_DIM / BM), THREADS, SMEM_BYTES>>>(
        wid, tgid, did, bh, Wo);

    reduce_out<<<B_DIM / 256, 256>>>(bo, out);
}